// round 13
// baseline (speedup 1.0000x reference)
#include <cuda_runtime.h>

#define B_  128
#define N_  512
#define D_  300
#define NC_ 10
#define DC_ 64
#define M_  640   // NC_*DC_

// Scratch (device globals; allocation-free per harness rules)
__device__ __align__(16) float g_y0p[B_*4*D_];    // colsum partials [B][4][D]
__device__ __align__(16) float g_v[B_*NC_*D_];    // v = log2e * W_i o_i  [B][NC][D]
__device__ __align__(16) float g_y[B_*NC_*D_];    // y = sum c x          [B][NC][D]
__device__ __align__(16) float g_Wt[M_*D_];       // W transposed [M][D]

// ---- packed f32x2 FMA (PTX-only; ptxas never auto-fuses) -------------------
__device__ __forceinline__ float2 ffma2(float2 a, float2 b, float2 c) {
    float2 d;
    asm("fma.rn.f32x2 %0, %1, %2, %3;"
        : "=l"(*reinterpret_cast<unsigned long long*>(&d))
        : "l"(*reinterpret_cast<const unsigned long long*>(&a)),
          "l"(*reinterpret_cast<const unsigned long long*>(&b)),
          "l"(*reinterpret_cast<const unsigned long long*>(&c)));
    return d;
}
// ---- raw MUFU ops (library exp2f/frcp are multi-instr without fast-math) ---
__device__ __forceinline__ float ex2_approx(float x) {
    float r; asm("ex2.approx.f32 %0, %1;" : "=f"(r) : "f"(x)); return r;
}
__device__ __forceinline__ float rcp_approx(float x) {
    float r; asm("rcp.approx.f32 %0, %1;" : "=f"(r) : "f"(x)); return r;
}

// ---------------------------------------------------------------------------
// Kernel 0 (fused prep): bid<512 -> colsum block; else W transpose tile.
// ---------------------------------------------------------------------------
__global__ void k_prep(const float* __restrict__ x, const float* __restrict__ W) {
    const int bid = blockIdx.x;
    const int tid = threadIdx.x;
    if (bid < 512) {                       // colsum: b = bid>>2, quarter = bid&3
        const int b = bid >> 2, q = bid & 3;
        const float* xb = x + (size_t)(b*N_ + q*128)*D_;
        for (int d = tid; d < D_; d += 256) {
            float a0=0.f, a1=0.f, a2=0.f, a3=0.f;
            #pragma unroll 4
            for (int r = 0; r < 128; r += 4) {
                a0 += xb[(size_t)(r+0)*D_ + d];
                a1 += xb[(size_t)(r+1)*D_ + d];
                a2 += xb[(size_t)(r+2)*D_ + d];
                a3 += xb[(size_t)(r+3)*D_ + d];
            }
            g_y0p[(b*4 + q)*D_ + d] = (a0+a1)+(a2+a3);
        }
    } else {                               // transpose tile
        __shared__ float t[32][33];
        const int tt = bid - 512;          // 0..199
        const int mx = (tt % 20)*32, dy = (tt / 20)*32;
        const int tx = tid & 31, ty = tid >> 5;
        #pragma unroll
        for (int r = 0; r < 4; ++r) {
            const int d = dy + ty + 8*r;
            if (d < D_) t[ty + 8*r][tx] = W[(size_t)d*M_ + mx + tx];
        }
        __syncthreads();
        #pragma unroll
        for (int r = 0; r < 4; ++r) {
            const int m = mx + ty + 8*r;
            const int d = dy + tx;
            if (d < D_) g_Wt[(size_t)m*D_ + d] = t[tx][ty + 8*r];
        }
    }
}

// ---------------------------------------------------------------------------
// Kernel 2: capsule reduce (R7 version; W stays L2-resident).
//   y -> s = W_i^T y -> o = squash(s) -> v = log2e * W_i o
// grid (NC, B/4) = (10,32), 256 threads, b-tile 4.
// ---------------------------------------------------------------------------
__global__ void __launch_bounds__(256) k_caps(const float* __restrict__ W,
                                              float* __restrict__ out, int phase) {
    __shared__ float ys[4][304];
    __shared__ float sp[4][4][64];   // [h][b][k] S-phase partials
    __shared__ float os[4][64];
    __shared__ float qw[8];
    const int i   = blockIdx.x;
    const int bt  = blockIdx.y*4;
    const int tid = threadIdx.x;

    if (phase == 0) {
        #pragma unroll
        for (int bb = 0; bb < 4; ++bb)
            for (int d = tid; d < D_; d += 256) {
                const float* p = g_y0p + (size_t)(bt+bb)*4*D_ + d;
                ys[bb][d] = 0.1f*((p[0] + p[D_]) + (p[2*D_] + p[3*D_]));
            }
    } else {
        #pragma unroll
        for (int bb = 0; bb < 4; ++bb)
            for (int d = tid; d < D_; d += 256)
                ys[bb][d] = g_y[((size_t)(bt+bb)*NC_ + i)*D_ + d];
    }
    __syncthreads();

    // S phase: thread (k = tid&63, h = tid>>6) covers d in [75h, 75h+75)
    {
        const int k = tid & 63, h = tid >> 6;
        const float* wp = W + (size_t)(75*h)*M_ + i*DC_ + k;
        float a0=0.f, a1=0.f, a2=0.f, a3=0.f;
        #pragma unroll 5
        for (int dd = 0; dd < 75; ++dd) {
            const float wv = wp[(size_t)dd*M_];
            const int d = 75*h + dd;
            a0 = fmaf(wv, ys[0][d], a0);
            a1 = fmaf(wv, ys[1][d], a1);
            a2 = fmaf(wv, ys[2][d], a2);
            a3 = fmaf(wv, ys[3][d], a3);
        }
        sp[h][0][k] = a0; sp[h][1][k] = a1; sp[h][2][k] = a2; sp[h][3][k] = a3;
    }
    __syncthreads();

    // combine + squash: thread tid -> (b = tid>>6, k = tid&63)
    {
        const int b = tid >> 6, k = tid & 63;
        const float s = (sp[0][b][k] + sp[1][b][k]) + (sp[2][b][k] + sp[3][b][k]);
        float q = s*s;
        #pragma unroll
        for (int off = 16; off; off >>= 1) q += __shfl_xor_sync(0xffffffffu, q, off);
        const int w = tid >> 5;
        if ((tid & 31) == 0) qw[w] = q;
        __syncthreads();
        const float ri = rsqrtf(qw[2*b] + qw[2*b+1] + 1e-7f);
        const float o = s * ri;
        os[b][k] = o;
        if (phase == 2) out[((size_t)(bt+b)*NC_ + i)*DC_ + k] = o;
    }
    __syncthreads();

    // V phase: v[b][d] = log2e * sum_k Wt[i*64+k][d] * o[b][k]
    if (phase != 2) {
        const float L2E = 1.44269504f;
        for (int d = tid; d < D_; d += 256) {
            const float* wt = g_Wt + (size_t)(i*DC_)*D_ + d;
            float a0=0.f, a1=0.f, a2=0.f, a3=0.f;
            #pragma unroll 8
            for (int k = 0; k < 64; ++k) {
                const float wv = wt[(size_t)k*D_];
                a0 = fmaf(wv, os[0][k], a0);
                a1 = fmaf(wv, os[1][k], a1);
                a2 = fmaf(wv, os[2][k], a2);
                a3 = fmaf(wv, os[3][k], a3);
            }
            g_v[((size_t)(bt+0)*NC_ + i)*D_ + d] = a0 * L2E;
            g_v[((size_t)(bt+1)*NC_ + i)*D_ + d] = a1 * L2E;
            g_v[((size_t)(bt+2)*NC_ + i)*D_ + d] = a2 * L2E;
            g_v[((size_t)(bt+3)*NC_ + i)*D_ + d] = a3 * L2E;
        }
    }
}

// ---------------------------------------------------------------------------
// Kernel 3 (v4): two-phase routing. grid (B), 384 threads (12 warps).
// Phase A (needs vr, no yr): dots -> softmax -> c to smem.   ~155 regs
// Phase B (needs yr, no vr): re-read x (L2-hit), y += c*x.   ~130 regs
// Splitting kills the 255-reg cap that held R7 at 8 warps/SM.
// ---------------------------------------------------------------------------
#define CSTR 12   // c row stride (floats); 48B -> 16B-aligned vector LDS
__global__ void __launch_bounds__(384, 1) k_main(const float* __restrict__ x) {
    extern __shared__ float sm[];
    float* cs   = sm;               // [N_][CSTR]  24576 B
    float* slab = sm + N_*CSTR;     // [6][NC_][D_] 72000 B
    const int b    = blockIdx.x;
    const int tid  = threadIdx.x;
    const int w    = tid >> 5;
    const int lane = tid & 31;
    const bool tl22 = (lane < 22);

    const int beg = (w < 8) ? w*43 : 344 + (w - 8)*42;
    const int end = (w < 8) ? beg + 43 : beg + 42;
    const float* xb = x + (size_t)b*N_*D_;

    // ---------------- Phase A: dots + softmax -> c ----------------
    {
        const float* vb = g_v + (size_t)b*NC_*D_;
        float2 vr[NC_][5];
        #pragma unroll
        for (int i = 0; i < NC_; ++i) {
            #pragma unroll
            for (int t = 0; t < 4; ++t)
                vr[i][t] = *(const float2*)(vb + i*D_ + 2*lane + 64*t);
            vr[i][4] = tl22 ? *(const float2*)(vb + i*D_ + 2*lane + 256)
                            : make_float2(0.f, 0.f);
        }

        int j = beg;
        for (; j + 1 < end; j += 2) {
            const float* xrA = xb + (size_t)j*D_;
            const float* xrB = xrA + D_;
            float2 xqA[5], xqB[5];
            #pragma unroll
            for (int t = 0; t < 4; ++t) {
                xqA[t] = *(const float2*)(xrA + 2*lane + 64*t);
                xqB[t] = *(const float2*)(xrB + 2*lane + 64*t);
            }
            xqA[4] = tl22 ? *(const float2*)(xrA + 2*lane + 256) : make_float2(0.f, 0.f);
            xqB[4] = tl22 ? *(const float2*)(xrB + 2*lane + 256) : make_float2(0.f, 0.f);

            float tlA[NC_], tlB[NC_];
            #pragma unroll
            for (int i = 0; i < NC_; ++i) {
                float2 aA = make_float2(0.f, 0.f), aB = make_float2(0.f, 0.f);
                #pragma unroll
                for (int t = 0; t < 5; ++t) {
                    aA = ffma2(xqA[t], vr[i][t], aA);
                    aB = ffma2(xqB[t], vr[i][t], aB);
                }
                tlA[i] = aA.x + aA.y;
                tlB[i] = aB.x + aB.y;
            }
            #pragma unroll
            for (int off = 16; off; off >>= 1) {
                #pragma unroll
                for (int i = 0; i < NC_; ++i) {
                    tlA[i] += __shfl_xor_sync(0xffffffffu, tlA[i], off);
                    tlB[i] += __shfl_xor_sync(0xffffffffu, tlB[i], off);
                }
            }
            #pragma unroll
            for (int i = 0; i < NC_; ++i) { tlA[i] = ex2_approx(tlA[i]); tlB[i] = ex2_approx(tlB[i]); }
            float sA = (((tlA[0]+tlA[1])+(tlA[2]+tlA[3]))+((tlA[4]+tlA[5])+(tlA[6]+tlA[7])))+(tlA[8]+tlA[9]);
            float sB = (((tlB[0]+tlB[1])+(tlB[2]+tlB[3]))+((tlB[4]+tlB[5])+(tlB[6]+tlB[7])))+(tlB[8]+tlB[9]);
            const float rA = rcp_approx(sA), rB = rcp_approx(sB);
            #pragma unroll
            for (int i = 0; i < NC_; ++i) {
                if (lane == i) {                       // static predicate, no spill
                    cs[j*CSTR + i]     = tlA[i]*rA;
                    cs[(j+1)*CSTR + i] = tlB[i]*rB;
                }
            }
        }
        if (j < end) {                                  // odd tail row
            const float* xr = xb + (size_t)j*D_;
            float2 xq[5];
            #pragma unroll
            for (int t = 0; t < 4; ++t) xq[t] = *(const float2*)(xr + 2*lane + 64*t);
            xq[4] = tl22 ? *(const float2*)(xr + 2*lane + 256) : make_float2(0.f, 0.f);
            float tl[NC_];
            #pragma unroll
            for (int i = 0; i < NC_; ++i) {
                float2 a = make_float2(0.f, 0.f);
                #pragma unroll
                for (int t = 0; t < 5; ++t) a = ffma2(xq[t], vr[i][t], a);
                tl[i] = a.x + a.y;
            }
            #pragma unroll
            for (int off = 16; off; off >>= 1)
                #pragma unroll
                for (int i = 0; i < NC_; ++i)
                    tl[i] += __shfl_xor_sync(0xffffffffu, tl[i], off);
            #pragma unroll
            for (int i = 0; i < NC_; ++i) tl[i] = ex2_approx(tl[i]);
            float s = (((tl[0]+tl[1])+(tl[2]+tl[3]))+((tl[4]+tl[5])+(tl[6]+tl[7])))+(tl[8]+tl[9]);
            const float r = rcp_approx(s);
            #pragma unroll
            for (int i = 0; i < NC_; ++i)
                if (lane == i) cs[j*CSTR + i] = tl[i]*r;
        }
    }
    __syncthreads();

    // ---------------- Phase B: y += c * x (no butterflies) ----------------
    {
        float2 yr[NC_][5];
        #pragma unroll
        for (int i = 0; i < NC_; ++i)
            #pragma unroll
            for (int t = 0; t < 5; ++t) yr[i][t] = make_float2(0.f, 0.f);

        for (int j = beg; j < end; ++j) {
            const float* xr = xb + (size_t)j*D_;
            float2 xq[5];
            #pragma unroll
            for (int t = 0; t < 4; ++t) xq[t] = *(const float2*)(xr + 2*lane + 64*t);
            xq[4] = tl22 ? *(const float2*)(xr + 2*lane + 256) : make_float2(0.f, 0.f);

            // broadcast vector loads of this row's 10 coefficients
            const float4 c03 = *(const float4*)(cs + j*CSTR);
            const float4 c47 = *(const float4*)(cs + j*CSTR + 4);
            const float2 c89 = *(const float2*)(cs + j*CSTR + 8);
            const float cv[NC_] = {c03.x, c03.y, c03.z, c03.w,
                                   c47.x, c47.y, c47.z, c47.w,
                                   c89.x, c89.y};
            #pragma unroll
            for (int i = 0; i < NC_; ++i) {
                const float2 c2 = make_float2(cv[i], cv[i]);
                #pragma unroll
                for (int t = 0; t < 5; ++t) yr[i][t] = ffma2(c2, xq[t], yr[i][t]);
            }
        }

        // merge 12 warp partials: warps 0-5 store slabs, 6-11 add into them
        if (w < 6) {
            #pragma unroll
            for (int i = 0; i < NC_; ++i)
                #pragma unroll
                for (int t = 0; t < 5; ++t) {
                    const int d = 2*lane + 64*t;
                    if (d < D_) *(float2*)&slab[(w*NC_ + i)*D_ + d] = yr[i][t];
                }
        }
        __syncthreads();
        if (w >= 6) {
            #pragma unroll
            for (int i = 0; i < NC_; ++i)
                #pragma unroll
                for (int t = 0; t < 5; ++t) {
                    const int d = 2*lane + 64*t;
                    if (d < D_) {
                        float2* p = (float2*)&slab[((w-6)*NC_ + i)*D_ + d];
                        float2 v0 = *p;
                        v0.x += yr[i][t].x; v0.y += yr[i][t].y;
                        *p = v0;
                    }
                }
        }
        __syncthreads();
    }
    {
        float* yo = g_y + (size_t)b*NC_*D_;
        for (int idx = tid; idx < NC_*D_; idx += 384) {
            const float v0 = slab[idx]            + slab[NC_*D_   + idx];
            const float v1 = slab[2*NC_*D_ + idx] + slab[3*NC_*D_ + idx];
            const float v2 = slab[4*NC_*D_ + idx] + slab[5*NC_*D_ + idx];
            yo[idx] = (v0 + v1) + v2;
        }
    }
}

// ---------------------------------------------------------------------------
extern "C" void kernel_launch(void* const* d_in, const int* in_sizes, int n_in,
                              void* d_out, int out_size) {
    const float* x = (const float*)d_in[0];
    const float* W = (const float*)d_in[1];
    if (n_in >= 2 && in_sizes[0] == D_*M_) {    // guard against input-order swap
        x = (const float*)d_in[1];
        W = (const float*)d_in[0];
    }
    float* out = (float*)d_out;

    const int MAIN_SMEM = (N_*CSTR + 6*NC_*D_) * (int)sizeof(float);  // ~96.6 KB
    cudaFuncSetAttribute(k_main, cudaFuncAttributeMaxDynamicSharedMemorySize, MAIN_SMEM);

    // prep: colsum (512 blocks) + W transpose (200 blocks), fused
    k_prep<<<712, 256>>>(x, W);
    // iter 0: c uniform (=0.1) -> y = 0.1*colsum -> o0, v0
    k_caps<<<dim3(NC_, B_/4), 256>>>(W, out, 0);
    // iters 1..4: c = softmax(x.v) -> y; y -> o -> v  (iter 4 writes output)
    for (int it = 1; it <= 4; ++it) {
        k_main<<<B_, 384, MAIN_SMEM>>>(x);
        k_caps<<<dim3(NC_, B_/4), 256>>>(W, out, it == 4 ? 2 : 1);
    }
}

// round 14
// speedup vs baseline: 1.5752x; 1.5752x over previous
#include <cuda_runtime.h>

#define B_  128
#define N_  512
#define D_  300
#define NC_ 10
#define DC_ 64
#define M_  640   // NC_*DC_

// Scratch (device globals; allocation-free per harness rules)
__device__ __align__(16) float g_y0p[B_*4*D_];    // colsum partials [B][4][D]
__device__ __align__(16) float g_v[B_*NC_*D_];    // v = log2e * W_i o_i  [B][NC][D]
__device__ __align__(16) float g_y[B_*NC_*D_];    // y = sum c x          [B][NC][D]
__device__ __align__(16) float g_Wt[M_*D_];       // W transposed [M][D]

// ---- packed f32x2 FMA (PTX-only; ptxas never auto-fuses) -------------------
__device__ __forceinline__ float2 ffma2(float2 a, float2 b, float2 c) {
    float2 d;
    asm("fma.rn.f32x2 %0, %1, %2, %3;"
        : "=l"(*reinterpret_cast<unsigned long long*>(&d))
        : "l"(*reinterpret_cast<const unsigned long long*>(&a)),
          "l"(*reinterpret_cast<const unsigned long long*>(&b)),
          "l"(*reinterpret_cast<const unsigned long long*>(&c)));
    return d;
}
// ---- raw MUFU ops (library exp2f/frcp are multi-instr without fast-math) ---
__device__ __forceinline__ float ex2_approx(float x) {
    float r; asm("ex2.approx.f32 %0, %1;" : "=f"(r) : "f"(x)); return r;
}
__device__ __forceinline__ float rcp_approx(float x) {
    float r; asm("rcp.approx.f32 %0, %1;" : "=f"(r) : "f"(x)); return r;
}

// ---------------------------------------------------------------------------
// Kernel 0 (fused prep): bid<512 -> colsum block; else W transpose tile.
// ---------------------------------------------------------------------------
__global__ void k_prep(const float* __restrict__ x, const float* __restrict__ W) {
    const int bid = blockIdx.x;
    const int tid = threadIdx.x;
    if (bid < 512) {                       // colsum: b = bid>>2, quarter = bid&3
        const int b = bid >> 2, q = bid & 3;
        const float* xb = x + (size_t)(b*N_ + q*128)*D_;
        for (int d = tid; d < D_; d += 256) {
            float a0=0.f, a1=0.f, a2=0.f, a3=0.f;
            #pragma unroll 4
            for (int r = 0; r < 128; r += 4) {
                a0 += xb[(size_t)(r+0)*D_ + d];
                a1 += xb[(size_t)(r+1)*D_ + d];
                a2 += xb[(size_t)(r+2)*D_ + d];
                a3 += xb[(size_t)(r+3)*D_ + d];
            }
            g_y0p[(b*4 + q)*D_ + d] = (a0+a1)+(a2+a3);
        }
    } else {                               // transpose tile
        __shared__ float t[32][33];
        const int tt = bid - 512;          // 0..199
        const int mx = (tt % 20)*32, dy = (tt / 20)*32;
        const int tx = tid & 31, ty = tid >> 5;
        #pragma unroll
        for (int r = 0; r < 4; ++r) {
            const int d = dy + ty + 8*r;
            if (d < D_) t[ty + 8*r][tx] = W[(size_t)d*M_ + mx + tx];
        }
        __syncthreads();
        #pragma unroll
        for (int r = 0; r < 4; ++r) {
            const int m = mx + ty + 8*r;
            const int d = dy + tx;
            if (d < D_) g_Wt[(size_t)m*D_ + d] = t[tx][ty + 8*r];
        }
    }
}

// ---------------------------------------------------------------------------
// Kernel 2 (b-tile 8): capsule reduce, W L2-resident (no W smem).
//   y -> s = W_i^T y -> o = squash(s) -> v = log2e * W_i o
// grid (NC, B/8) = (10,16), 256 threads. Each W load feeds 8 FMA (one per
// batch); squash is fully warp-local (warp w owns batch bt+w).
// phase 0: y=0.1*colsum -> v.  phase 1: y=g_y -> v.  phase 2: y=g_y -> out.
// ---------------------------------------------------------------------------
__global__ void __launch_bounds__(256) k_caps(const float* __restrict__ W,
                                              float* __restrict__ out, int phase) {
    __shared__ float ys[8][304];
    __shared__ float sp[4][8][64];   // [h][b][k] S-phase partials
    __shared__ float os[8][64];
    const int i   = blockIdx.x;
    const int bt  = blockIdx.y*8;
    const int tid = threadIdx.x;

    if (phase == 0) {
        #pragma unroll
        for (int bb = 0; bb < 8; ++bb)
            for (int d = tid; d < D_; d += 256) {
                const float* p = g_y0p + (size_t)(bt+bb)*4*D_ + d;
                ys[bb][d] = 0.1f*((p[0] + p[D_]) + (p[2*D_] + p[3*D_]));
            }
    } else {
        #pragma unroll
        for (int bb = 0; bb < 8; ++bb)
            for (int d = tid; d < D_; d += 256)
                ys[bb][d] = g_y[((size_t)(bt+bb)*NC_ + i)*D_ + d];
    }
    __syncthreads();

    // S phase: thread (k = tid&63, h = tid>>6) covers d in [75h, 75h+75),
    // 8 batches per W load (ys loads broadcast across the warp).
    {
        const int k = tid & 63, h = tid >> 6;
        const float* wp = W + (size_t)(75*h)*M_ + i*DC_ + k;
        float a0=0.f,a1=0.f,a2=0.f,a3=0.f,a4=0.f,a5=0.f,a6=0.f,a7=0.f;
        #pragma unroll 3
        for (int dd = 0; dd < 75; ++dd) {
            const float wv = wp[(size_t)dd*M_];
            const int d = 75*h + dd;
            a0 = fmaf(wv, ys[0][d], a0);
            a1 = fmaf(wv, ys[1][d], a1);
            a2 = fmaf(wv, ys[2][d], a2);
            a3 = fmaf(wv, ys[3][d], a3);
            a4 = fmaf(wv, ys[4][d], a4);
            a5 = fmaf(wv, ys[5][d], a5);
            a6 = fmaf(wv, ys[6][d], a6);
            a7 = fmaf(wv, ys[7][d], a7);
        }
        sp[h][0][k]=a0; sp[h][1][k]=a1; sp[h][2][k]=a2; sp[h][3][k]=a3;
        sp[h][4][k]=a4; sp[h][5][k]=a5; sp[h][6][k]=a6; sp[h][7][k]=a7;
    }
    __syncthreads();

    // squash: warp w owns batch bt+w; lane handles k=lane and k=lane+32
    {
        const int w = tid >> 5, lane = tid & 31;
        const float sl = (sp[0][w][lane]      + sp[1][w][lane])
                       + (sp[2][w][lane]      + sp[3][w][lane]);
        const float sh = (sp[0][w][lane+32]   + sp[1][w][lane+32])
                       + (sp[2][w][lane+32]   + sp[3][w][lane+32]);
        float q = fmaf(sl, sl, sh*sh);
        #pragma unroll
        for (int off = 16; off; off >>= 1) q += __shfl_xor_sync(0xffffffffu, q, off);
        const float ri = rsqrtf(q + 1e-7f);
        const float ol = sl*ri, oh = sh*ri;
        os[w][lane]      = ol;
        os[w][lane + 32] = oh;
        if (phase == 2) {
            float* op = out + ((size_t)(bt+w)*NC_ + i)*DC_;
            op[lane]      = ol;
            op[lane + 32] = oh;
        }
    }
    __syncthreads();

    // V phase: v[b][d] = log2e * sum_k Wt[i*64+k][d] * o[b][k]
    // thread owns d; each Wt load feeds 8 FMA (os loads broadcast).
    if (phase != 2) {
        const float L2E = 1.44269504f;
        for (int d = tid; d < D_; d += 256) {
            const float* wt = g_Wt + (size_t)(i*DC_)*D_ + d;
            float a0=0.f,a1=0.f,a2=0.f,a3=0.f,a4=0.f,a5=0.f,a6=0.f,a7=0.f;
            #pragma unroll 4
            for (int k = 0; k < 64; ++k) {
                const float wv = wt[(size_t)k*D_];
                a0 = fmaf(wv, os[0][k], a0);
                a1 = fmaf(wv, os[1][k], a1);
                a2 = fmaf(wv, os[2][k], a2);
                a3 = fmaf(wv, os[3][k], a3);
                a4 = fmaf(wv, os[4][k], a4);
                a5 = fmaf(wv, os[5][k], a5);
                a6 = fmaf(wv, os[6][k], a6);
                a7 = fmaf(wv, os[7][k], a7);
            }
            g_v[((size_t)(bt+0)*NC_ + i)*D_ + d] = a0 * L2E;
            g_v[((size_t)(bt+1)*NC_ + i)*D_ + d] = a1 * L2E;
            g_v[((size_t)(bt+2)*NC_ + i)*D_ + d] = a2 * L2E;
            g_v[((size_t)(bt+3)*NC_ + i)*D_ + d] = a3 * L2E;
            g_v[((size_t)(bt+4)*NC_ + i)*D_ + d] = a4 * L2E;
            g_v[((size_t)(bt+5)*NC_ + i)*D_ + d] = a5 * L2E;
            g_v[((size_t)(bt+6)*NC_ + i)*D_ + d] = a6 * L2E;
            g_v[((size_t)(bt+7)*NC_ + i)*D_ + d] = a7 * L2E;
        }
    }
}

// ---------------------------------------------------------------------------
// Kernel 3: main routing pass — EXACT R7 structure (best measured: 49.8us).
// grid (B), 256 threads. v/y register-resident, FFMA2, ILP-2, raw EX2/RCP.
// ---------------------------------------------------------------------------
__global__ void __launch_bounds__(256, 1) k_main(const float* __restrict__ x) {
    __shared__ __align__(16) float slab[4][NC_][D_];   // cross-warp y merge
    const int b    = blockIdx.x;
    const int w    = threadIdx.x >> 5;
    const int lane = threadIdx.x & 31;
    const bool tl22 = (lane < 22);

    const float* vb = g_v + (size_t)b*NC_*D_;
    float2 vr[NC_][5];
    #pragma unroll
    for (int i = 0; i < NC_; ++i) {
        #pragma unroll
        for (int t = 0; t < 4; ++t)
            vr[i][t] = *(const float2*)(vb + i*D_ + 2*lane + 64*t);
        vr[i][4] = tl22 ? *(const float2*)(vb + i*D_ + 2*lane + 256)
                        : make_float2(0.f, 0.f);
    }
    float2 yr[NC_][5];
    #pragma unroll
    for (int i = 0; i < NC_; ++i)
        #pragma unroll
        for (int t = 0; t < 5; ++t) yr[i][t] = make_float2(0.f, 0.f);

    const float* xb = x + (size_t)b*N_*D_;
    for (int j = w*64; j < w*64 + 64; j += 2) {
        const float* xrA = xb + (size_t)j*D_;
        const float* xrB = xrA + D_;
        float2 xqA[5], xqB[5];
        #pragma unroll
        for (int t = 0; t < 4; ++t) {
            xqA[t] = *(const float2*)(xrA + 2*lane + 64*t);
            xqB[t] = *(const float2*)(xrB + 2*lane + 64*t);
        }
        xqA[4] = tl22 ? *(const float2*)(xrA + 2*lane + 256) : make_float2(0.f, 0.f);
        xqB[4] = tl22 ? *(const float2*)(xrB + 2*lane + 256) : make_float2(0.f, 0.f);

        float tlA[NC_], tlB[NC_];
        #pragma unroll
        for (int i = 0; i < NC_; ++i) {
            float2 aA = make_float2(0.f, 0.f), aB = make_float2(0.f, 0.f);
            #pragma unroll
            for (int t = 0; t < 5; ++t) {
                aA = ffma2(xqA[t], vr[i][t], aA);
                aB = ffma2(xqB[t], vr[i][t], aB);
            }
            tlA[i] = aA.x + aA.y;
            tlB[i] = aB.x + aB.y;
        }
        #pragma unroll
        for (int off = 16; off; off >>= 1) {
            #pragma unroll
            for (int i = 0; i < NC_; ++i) {
                tlA[i] += __shfl_xor_sync(0xffffffffu, tlA[i], off);
                tlB[i] += __shfl_xor_sync(0xffffffffu, tlB[i], off);
            }
        }
        #pragma unroll
        for (int i = 0; i < NC_; ++i) { tlA[i] = ex2_approx(tlA[i]); tlB[i] = ex2_approx(tlB[i]); }
        float sA = (((tlA[0]+tlA[1])+(tlA[2]+tlA[3]))+((tlA[4]+tlA[5])+(tlA[6]+tlA[7])))+(tlA[8]+tlA[9]);
        float sB = (((tlB[0]+tlB[1])+(tlB[2]+tlB[3]))+((tlB[4]+tlB[5])+(tlB[6]+tlB[7])))+(tlB[8]+tlB[9]);
        const float rA = rcp_approx(sA), rB = rcp_approx(sB);
        #pragma unroll
        for (int i = 0; i < NC_; ++i) {
            const float2 cA = make_float2(tlA[i]*rA, tlA[i]*rA);
            const float2 cB = make_float2(tlB[i]*rB, tlB[i]*rB);
            #pragma unroll
            for (int t = 0; t < 5; ++t)
                yr[i][t] = ffma2(cB, xqB[t], ffma2(cA, xqA[t], yr[i][t]));
        }
    }

    // merge 8 warp partials: warps 0-3 store slabs, warps 4-7 add into them
    if (w < 4) {
        #pragma unroll
        for (int i = 0; i < NC_; ++i)
            #pragma unroll
            for (int t = 0; t < 5; ++t) {
                const int d = 2*lane + 64*t;
                if (d < D_) *(float2*)&slab[w][i][d] = yr[i][t];
            }
    }
    __syncthreads();
    if (w >= 4) {
        #pragma unroll
        for (int i = 0; i < NC_; ++i)
            #pragma unroll
            for (int t = 0; t < 5; ++t) {
                const int d = 2*lane + 64*t;
                if (d < D_) {
                    float2* p = (float2*)&slab[w-4][i][d];
                    float2 v0 = *p;
                    v0.x += yr[i][t].x; v0.y += yr[i][t].y;
                    *p = v0;
                }
            }
    }
    __syncthreads();
    float* yo = g_y + (size_t)b*NC_*D_;
    const float* s0 = &slab[0][0][0];
    const float* s1 = &slab[1][0][0];
    const float* s2 = &slab[2][0][0];
    const float* s3 = &slab[3][0][0];
    for (int idx = threadIdx.x; idx < NC_*D_; idx += 256)
        yo[idx] = (s0[idx] + s1[idx]) + (s2[idx] + s3[idx]);
}

// ---------------------------------------------------------------------------
extern "C" void kernel_launch(void* const* d_in, const int* in_sizes, int n_in,
                              void* d_out, int out_size) {
    const float* x = (const float*)d_in[0];
    const float* W = (const float*)d_in[1];
    if (n_in >= 2 && in_sizes[0] == D_*M_) {    // guard against input-order swap
        x = (const float*)d_in[1];
        W = (const float*)d_in[0];
    }
    float* out = (float*)d_out;

    // prep: colsum (512 blocks) + W transpose (200 blocks), fused
    k_prep<<<712, 256>>>(x, W);
    // iter 0: c uniform (=0.1) -> y = 0.1*colsum -> o0, v0
    k_caps<<<dim3(NC_, B_/8), 256>>>(W, out, 0);
    // iters 1..4: c = softmax(x.v) -> y; y -> o -> v  (iter 4 writes output)
    for (int it = 1; it <= 4; ++it) {
        k_main<<<B_, 256>>>(x);
        k_caps<<<dim3(NC_, B_/8), 256>>>(W, out, it == 4 ? 2 : 1);
    }
}

// round 15
// speedup vs baseline: 1.5876x; 1.0079x over previous
#include <cuda_runtime.h>

#define B_  128
#define N_  512
#define D_  300
#define NC_ 10
#define DC_ 64
#define M_  640   // NC_*DC_

// Scratch (device globals; allocation-free per harness rules)
__device__ __align__(16) float g_y0p[B_*4*D_];    // colsum partials [B][4][D]
__device__ __align__(16) float g_v[B_*NC_*D_];    // v = log2e * W_i o_i  [B][NC][D]
__device__ __align__(16) float g_y[B_*NC_*D_];    // y = sum c x          [B][NC][D]
__device__ __align__(16) float g_Wt[M_*D_];       // W transposed [M][D]

// ---- packed f32x2 FMA (PTX-only; ptxas never auto-fuses) -------------------
__device__ __forceinline__ float2 ffma2(float2 a, float2 b, float2 c) {
    float2 d;
    asm("fma.rn.f32x2 %0, %1, %2, %3;"
        : "=l"(*reinterpret_cast<unsigned long long*>(&d))
        : "l"(*reinterpret_cast<const unsigned long long*>(&a)),
          "l"(*reinterpret_cast<const unsigned long long*>(&b)),
          "l"(*reinterpret_cast<const unsigned long long*>(&c)));
    return d;
}
// ---- raw MUFU ops (library exp2f/frcp are multi-instr without fast-math) ---
__device__ __forceinline__ float ex2_approx(float x) {
    float r; asm("ex2.approx.f32 %0, %1;" : "=f"(r) : "f"(x)); return r;
}
__device__ __forceinline__ float rcp_approx(float x) {
    float r; asm("rcp.approx.f32 %0, %1;" : "=f"(r) : "f"(x)); return r;
}

// ---------------------------------------------------------------------------
// Kernel 0 (fused prep): bid<512 -> colsum block; else W transpose tile.
// ---------------------------------------------------------------------------
__global__ void k_prep(const float* __restrict__ x, const float* __restrict__ W) {
    const int bid = blockIdx.x;
    const int tid = threadIdx.x;
    if (bid < 512) {                       // colsum: b = bid>>2, quarter = bid&3
        const int b = bid >> 2, q = bid & 3;
        const float* xb = x + (size_t)(b*N_ + q*128)*D_;
        for (int d = tid; d < D_; d += 256) {
            float a0=0.f, a1=0.f, a2=0.f, a3=0.f;
            #pragma unroll 4
            for (int r = 0; r < 128; r += 4) {
                a0 += xb[(size_t)(r+0)*D_ + d];
                a1 += xb[(size_t)(r+1)*D_ + d];
                a2 += xb[(size_t)(r+2)*D_ + d];
                a3 += xb[(size_t)(r+3)*D_ + d];
            }
            g_y0p[(b*4 + q)*D_ + d] = (a0+a1)+(a2+a3);
        }
    } else {                               // transpose tile
        __shared__ float t[32][33];
        const int tt = bid - 512;          // 0..199
        const int mx = (tt % 20)*32, dy = (tt / 20)*32;
        const int tx = tid & 31, ty = tid >> 5;
        #pragma unroll
        for (int r = 0; r < 4; ++r) {
            const int d = dy + ty + 8*r;
            if (d < D_) t[ty + 8*r][tx] = W[(size_t)d*M_ + mx + tx];
        }
        __syncthreads();
        #pragma unroll
        for (int r = 0; r < 4; ++r) {
            const int m = mx + ty + 8*r;
            const int d = dy + tx;
            if (d < D_) g_Wt[(size_t)m*D_ + d] = t[tx][ty + 8*r];
        }
    }
}

// ---------------------------------------------------------------------------
// Kernel 2: capsule reduce — FROZEN R7 version (measured best: b-tile 4,
// grid (10,32) = 320 blocks, W L2-resident, no W smem).
//   y -> s = W_i^T y -> o = squash(s) -> v = log2e * W_i o
// ---------------------------------------------------------------------------
__global__ void __launch_bounds__(256) k_caps(const float* __restrict__ W,
                                              float* __restrict__ out, int phase) {
    __shared__ float ys[4][304];
    __shared__ float sp[4][4][64];   // [h][b][k] S-phase partials
    __shared__ float os[4][64];
    __shared__ float qw[8];
    const int i   = blockIdx.x;
    const int bt  = blockIdx.y*4;
    const int tid = threadIdx.x;

    if (phase == 0) {
        #pragma unroll
        for (int bb = 0; bb < 4; ++bb)
            for (int d = tid; d < D_; d += 256) {
                const float* p = g_y0p + (size_t)(bt+bb)*4*D_ + d;
                ys[bb][d] = 0.1f*((p[0] + p[D_]) + (p[2*D_] + p[3*D_]));
            }
    } else {
        #pragma unroll
        for (int bb = 0; bb < 4; ++bb)
            for (int d = tid; d < D_; d += 256)
                ys[bb][d] = g_y[((size_t)(bt+bb)*NC_ + i)*D_ + d];
    }
    __syncthreads();

    // S phase: thread (k = tid&63, h = tid>>6) covers d in [75h, 75h+75)
    {
        const int k = tid & 63, h = tid >> 6;
        const float* wp = W + (size_t)(75*h)*M_ + i*DC_ + k;
        float a0=0.f, a1=0.f, a2=0.f, a3=0.f;
        #pragma unroll 5
        for (int dd = 0; dd < 75; ++dd) {
            const float wv = wp[(size_t)dd*M_];
            const int d = 75*h + dd;
            a0 = fmaf(wv, ys[0][d], a0);
            a1 = fmaf(wv, ys[1][d], a1);
            a2 = fmaf(wv, ys[2][d], a2);
            a3 = fmaf(wv, ys[3][d], a3);
        }
        sp[h][0][k] = a0; sp[h][1][k] = a1; sp[h][2][k] = a2; sp[h][3][k] = a3;
    }
    __syncthreads();

    // combine + squash: thread tid -> (b = tid>>6, k = tid&63)
    {
        const int b = tid >> 6, k = tid & 63;
        const float s = (sp[0][b][k] + sp[1][b][k]) + (sp[2][b][k] + sp[3][b][k]);
        float q = s*s;
        #pragma unroll
        for (int off = 16; off; off >>= 1) q += __shfl_xor_sync(0xffffffffu, q, off);
        const int w = tid >> 5;
        if ((tid & 31) == 0) qw[w] = q;
        __syncthreads();
        const float ri = rsqrtf(qw[2*b] + qw[2*b+1] + 1e-7f);
        const float o = s * ri;
        os[b][k] = o;
        if (phase == 2) out[((size_t)(bt+b)*NC_ + i)*DC_ + k] = o;
    }
    __syncthreads();

    // V phase: v[b][d] = log2e * sum_k Wt[i*64+k][d] * o[b][k]
    if (phase != 2) {
        const float L2E = 1.44269504f;
        for (int d = tid; d < D_; d += 256) {
            const float* wt = g_Wt + (size_t)(i*DC_)*D_ + d;
            float a0=0.f, a1=0.f, a2=0.f, a3=0.f;
            #pragma unroll 8
            for (int k = 0; k < 64; ++k) {
                const float wv = wt[(size_t)k*D_];
                a0 = fmaf(wv, os[0][k], a0);
                a1 = fmaf(wv, os[1][k], a1);
                a2 = fmaf(wv, os[2][k], a2);
                a3 = fmaf(wv, os[3][k], a3);
            }
            g_v[((size_t)(bt+0)*NC_ + i)*D_ + d] = a0 * L2E;
            g_v[((size_t)(bt+1)*NC_ + i)*D_ + d] = a1 * L2E;
            g_v[((size_t)(bt+2)*NC_ + i)*D_ + d] = a2 * L2E;
            g_v[((size_t)(bt+3)*NC_ + i)*D_ + d] = a3 * L2E;
        }
    }
}

// ---------------------------------------------------------------------------
// Kernel 3 (v5): R7 math, software-pipelined. grid (B), 256 threads.
// ILP-1 rows with prefetch distance 2 (3 rotating x buffers): row j+2's
// LDGs issue ~2 row-bodies (~500 cyc) before first use, covering the
// ~577-cyc DRAM latency that held R7's issue at 42%.
// ---------------------------------------------------------------------------
__global__ void __launch_bounds__(256, 1) k_main(const float* __restrict__ x) {
    __shared__ __align__(16) float slab[4][NC_][D_];   // cross-warp y merge
    const int b    = blockIdx.x;
    const int w    = threadIdx.x >> 5;
    const int lane = threadIdx.x & 31;
    const bool tl22 = (lane < 22);

    const float* vb = g_v + (size_t)b*NC_*D_;
    float2 vr[NC_][5];
    #pragma unroll
    for (int i = 0; i < NC_; ++i) {
        #pragma unroll
        for (int t = 0; t < 4; ++t)
            vr[i][t] = *(const float2*)(vb + i*D_ + 2*lane + 64*t);
        vr[i][4] = tl22 ? *(const float2*)(vb + i*D_ + 2*lane + 256)
                        : make_float2(0.f, 0.f);
    }
    float2 yr[NC_][5];
    #pragma unroll
    for (int i = 0; i < NC_; ++i)
        #pragma unroll
        for (int t = 0; t < 5; ++t) yr[i][t] = make_float2(0.f, 0.f);

    const float* xb = x + (size_t)(b*N_ + w*64)*D_;   // warp's 64-row window

    float2 xq0[5], xq1[5], xq2[5];

    auto loadrow = [&](float2* dst, int l) {          // l in [0,63], clamped by caller
        const float* xr = xb + (size_t)l*D_;
        #pragma unroll
        for (int t = 0; t < 4; ++t) dst[t] = *(const float2*)(xr + 2*lane + 64*t);
        dst[4] = tl22 ? *(const float2*)(xr + 2*lane + 256) : make_float2(0.f, 0.f);
    };
    auto process = [&](const float2* xq) {
        float tl[NC_];
        #pragma unroll
        for (int i = 0; i < NC_; ++i) {
            float2 a = make_float2(0.f, 0.f);
            #pragma unroll
            for (int t = 0; t < 5; ++t) a = ffma2(xq[t], vr[i][t], a);
            tl[i] = a.x + a.y;
        }
        #pragma unroll
        for (int off = 16; off; off >>= 1) {
            #pragma unroll
            for (int i = 0; i < NC_; ++i)
                tl[i] += __shfl_xor_sync(0xffffffffu, tl[i], off);
        }
        #pragma unroll
        for (int i = 0; i < NC_; ++i) tl[i] = ex2_approx(tl[i]);
        float s = (((tl[0]+tl[1])+(tl[2]+tl[3]))+((tl[4]+tl[5])+(tl[6]+tl[7])))+(tl[8]+tl[9]);
        const float r = rcp_approx(s);
        #pragma unroll
        for (int i = 0; i < NC_; ++i) {
            const float c = tl[i] * r;
            const float2 c2 = make_float2(c, c);
            #pragma unroll
            for (int t = 0; t < 5; ++t) yr[i][t] = ffma2(c2, xq[t], yr[i][t]);
        }
    };

    loadrow(xq0, 0);
    loadrow(xq1, 1);
    #pragma unroll 1
    for (int k = 0; k < 63; k += 3) {                  // 21 iterations: rows 0..62
        loadrow(xq2, (k+2 <= 63) ? k+2 : 63); process(xq0);
        loadrow(xq0, (k+3 <= 63) ? k+3 : 63); process(xq1);
        loadrow(xq1, (k+4 <= 63) ? k+4 : 63); process(xq2);
    }
    process(xq0);                                      // row 63 (63 % 3 == 0)

    // merge 8 warp partials: warps 0-3 store slabs, warps 4-7 add into them
    if (w < 4) {
        #pragma unroll
        for (int i = 0; i < NC_; ++i)
            #pragma unroll
            for (int t = 0; t < 5; ++t) {
                const int d = 2*lane + 64*t;
                if (d < D_) *(float2*)&slab[w][i][d] = yr[i][t];
            }
    }
    __syncthreads();
    if (w >= 4) {
        #pragma unroll
        for (int i = 0; i < NC_; ++i)
            #pragma unroll
            for (int t = 0; t < 5; ++t) {
                const int d = 2*lane + 64*t;
                if (d < D_) {
                    float2* p = (float2*)&slab[w-4][i][d];
                    float2 v0 = *p;
                    v0.x += yr[i][t].x; v0.y += yr[i][t].y;
                    *p = v0;
                }
            }
    }
    __syncthreads();
    float* yo = g_y + (size_t)b*NC_*D_;
    const float* s0 = &slab[0][0][0];
    const float* s1 = &slab[1][0][0];
    const float* s2 = &slab[2][0][0];
    const float* s3 = &slab[3][0][0];
    for (int idx = threadIdx.x; idx < NC_*D_; idx += 256)
        yo[idx] = (s0[idx] + s1[idx]) + (s2[idx] + s3[idx]);
}

// ---------------------------------------------------------------------------
extern "C" void kernel_launch(void* const* d_in, const int* in_sizes, int n_in,
                              void* d_out, int out_size) {
    const float* x = (const float*)d_in[0];
    const float* W = (const float*)d_in[1];
    if (n_in >= 2 && in_sizes[0] == D_*M_) {    // guard against input-order swap
        x = (const float*)d_in[1];
        W = (const float*)d_in[0];
    }
    float* out = (float*)d_out;

    // prep: colsum (512 blocks) + W transpose (200 blocks), fused
    k_prep<<<712, 256>>>(x, W);
    // iter 0: c uniform (=0.1) -> y = 0.1*colsum -> o0, v0
    k_caps<<<dim3(NC_, B_/4), 256>>>(W, out, 0);
    // iters 1..4: c = softmax(x.v) -> y; y -> o -> v  (iter 4 writes output)
    for (int it = 1; it <= 4; ++it) {
        k_main<<<B_, 256>>>(x);
        k_caps<<<dim3(NC_, B_/4), 256>>>(W, out, it == 4 ? 2 : 1);
    }
}